// round 10
// baseline (speedup 1.0000x reference)
#include <cuda_runtime.h>

#define NV_MAX 50000
#define HDIM 64

// -------- scratch (no allocs allowed) --------
__device__ float g_A[NV_MAX * HDIM];
__device__ float g_B[NV_MAX * HDIM];
__device__ float g_P[NV_MAX * HDIM];
__device__ float g_Q[NV_MAX * HDIM];
__device__ float g_aggr[NV_MAX * HDIM];
__device__ float g_aggrp[NV_MAX * HDIM];

typedef unsigned long long ull_t;

__device__ __forceinline__ ull_t pack2(float lo, float hi) {
    ull_t r; asm("mov.b64 %0, {%1, %2};" : "=l"(r) : "f"(lo), "f"(hi)); return r;
}
__device__ __forceinline__ void unpack2(ull_t v, float& lo, float& hi) {
    asm("mov.b64 {%0, %1}, %2;" : "=f"(lo), "=f"(hi) : "l"(v));
}
__device__ __forceinline__ ull_t ffma2(ull_t a, ull_t b, ull_t c) {
    ull_t d; asm("fma.rn.f32x2 %0, %1, %2, %3;" : "=l"(d) : "l"(a), "l"(b), "l"(c)); return d;
}
__device__ __forceinline__ float tanh_f(float x) {
    float y; asm("tanh.approx.f32 %0, %1;" : "=f"(y) : "f"(x)); return y;
}
__device__ __forceinline__ float silu_f(float x) {
    return 0.5f * x * (1.0f + tanh_f(0.5f * x));   // single MUFU
}

// FFMA2 block: row-pairs come straight from LDS (no h packing);
// only W is splatted (4 MOV per k).
#define FFMA2_PBLOCK(hA, hB, wv)                                            \
    {                                                                       \
        float w0, w1, w2, w3;                                               \
        unpack2(wv.x, w0, w1); unpack2(wv.y, w2, w3);                       \
        ull_t ws0 = pack2(w0, w0), ws1 = pack2(w1, w1);                     \
        ull_t ws2 = pack2(w2, w2), ws3 = pack2(w3, w3);                     \
        acc[0][0] = ffma2(hA.x, ws0, acc[0][0]); acc[0][1] = ffma2(hA.x, ws1, acc[0][1]); \
        acc[0][2] = ffma2(hA.x, ws2, acc[0][2]); acc[0][3] = ffma2(hA.x, ws3, acc[0][3]); \
        acc[1][0] = ffma2(hA.y, ws0, acc[1][0]); acc[1][1] = ffma2(hA.y, ws1, acc[1][1]); \
        acc[1][2] = ffma2(hA.y, ws2, acc[1][2]); acc[1][3] = ffma2(hA.y, ws3, acc[1][3]); \
        acc[2][0] = ffma2(hB.x, ws0, acc[2][0]); acc[2][1] = ffma2(hB.x, ws1, acc[2][1]); \
        acc[2][2] = ffma2(hB.x, ws2, acc[2][2]); acc[2][3] = ffma2(hB.x, ws3, acc[2][3]); \
        acc[3][0] = ffma2(hB.y, ws0, acc[3][0]); acc[3][1] = ffma2(hB.y, ws1, acc[3][1]); \
        acc[3][2] = ffma2(hB.y, ws2, acc[3][2]); acc[3][3] = ffma2(hB.y, ws3, acc[3][3]); \
    }

// 8 rows x 4 cols per thread. Rows = two warp-contiguous quads at r0=4*tr and
// HALF+4*tr (conflict-free LDS.128). acc[p][c] f32x2: lo/hi = adjacent rows:
//   p=0 -> rows r0,r0+1   p=1 -> r0+2,r0+3   p=2 -> HALF+r0,HALF+r0+1   p=3 -> HALF+r0+2,+3
// Software-pipelined version (3-CTA kernels).
template <int K, int ISTRIDE, int WSTRIDE, int HALF>
__device__ __forceinline__ void gemm_p8x4(
    const float* __restrict__ inT, const float* __restrict__ W, ull_t acc[4][4])
{
    ulonglong2 hA = *(const ulonglong2*)(inT);
    ulonglong2 hB = *(const ulonglong2*)(inT + HALF);
    ulonglong2 wv = *(const ulonglong2*)(W);
    #pragma unroll 8
    for (int k = 0; k < K; k++) {
        ulonglong2 nhA, nhB, nwv;
        if (k + 1 < K) {
            nhA = *(const ulonglong2*)(inT + (k + 1) * ISTRIDE);
            nhB = *(const ulonglong2*)(inT + (k + 1) * ISTRIDE + HALF);
            nwv = *(const ulonglong2*)(W + (k + 1) * WSTRIDE);
        }
        FFMA2_PBLOCK(hA, hB, wv);
        hA = nhA; hB = nhB; wv = nwv;
    }
}

// No-prefetch variant (4-CTA edge kernel; latency hidden by 32 warps).
template <int K, int ISTRIDE, int WSTRIDE, int HALF>
__device__ __forceinline__ void gemm_p8x4_np(
    const float* __restrict__ inT, const float* __restrict__ W, ull_t acc[4][4])
{
    #pragma unroll 8
    for (int k = 0; k < K; k++) {
        ulonglong2 hA = *(const ulonglong2*)(inT + k * ISTRIDE);
        ulonglong2 hB = *(const ulonglong2*)(inT + k * ISTRIDE + HALF);
        ulonglong2 wv = *(const ulonglong2*)(W + k * WSTRIDE);
        FFMA2_PBLOCK(hA, hB, wv);
    }
}

__device__ __forceinline__ void zero_acc(ull_t acc[4][4]) {
    #pragma unroll
    for (int i = 0; i < 4; i++)
        #pragma unroll
        for (int j = 0; j < 4; j++) acc[i][j] = 0ULL;
}

// ============================================================
// Kernel 1 (fused): blockIdx.y==0 -> A,B (+zero aggr); ==1 -> P,Q
//   64 nodes/CTA; 128 out cols.
// ============================================================
__global__ void __launch_bounds__(256, 3) pre_kernel(
    const float* __restrict__ x, const float* __restrict__ pe,
    const float* __restrict__ msg_w1, const float* __restrict__ msg_b1,
    const float* __restrict__ mpos_w1, const float* __restrict__ mpos_b1,
    int N)
{
    extern __shared__ float sm[];
    float* sh_inT = sm;                   // [64][68]
    float* sh_W   = sh_inT + 64 * 68;     // [64][128]
    float* sh_b   = sh_W + 64 * 128;      // [128]

    int tid = threadIdx.x;
    int nb = blockIdx.x * 64;
    int tr = tid & 7, tc = tid >> 3;
    int r0 = 4 * tr, c0 = 4 * tc;

    ull_t acc[4][4];
    zero_acc(acc);
    float* dstA;
    float* dstB;

    if (blockIdx.y == 0) {
        if (tid < 128) sh_b[tid] = (tid < 64) ? msg_b1[tid] : 0.0f;
        for (int idx = tid; idx < 2048; idx += 256) {
            int n = idx & 63, s = (idx >> 6) & 15, which = idx >> 10;
            int gn = nb + n;
            if (gn < N) {
                float4* dst = (float4*)((which ? g_aggrp : g_aggr) + (size_t)gn * 64) + s;
                *dst = make_float4(0.f, 0.f, 0.f, 0.f);
            }
        }
        #pragma unroll 1
        for (int ch = 0; ch < 2; ch++) {
            __syncthreads();
            for (int idx = tid; idx < 64 * 128; idx += 256) {
                int k = idx >> 7, c = idx & 127;
                sh_W[idx] = (c < 64) ? msg_w1[(ch * 64 + k) * 64 + c]
                                     : msg_w1[(128 + ch * 64 + k) * 64 + (c - 64)];
            }
            const float* src = (ch == 0) ? x : pe;
            for (int idx = tid; idx < 16 * 64; idx += 256) {
                int n = idx & 63, k4 = idx >> 6;
                int gn = nb + n;
                float4 v = make_float4(0.f, 0.f, 0.f, 0.f);
                if (gn < N) v = *(const float4*)(src + (size_t)gn * 64 + 4 * k4);
                sh_inT[(4 * k4 + 0) * 68 + n] = v.x;
                sh_inT[(4 * k4 + 1) * 68 + n] = v.y;
                sh_inT[(4 * k4 + 2) * 68 + n] = v.z;
                sh_inT[(4 * k4 + 3) * 68 + n] = v.w;
            }
            __syncthreads();
            gemm_p8x4<64, 68, 128, 32>(sh_inT + r0, sh_W + c0, acc);
        }
        dstA = g_A; dstB = g_B;
    } else {
        if (tid < 128) sh_b[tid] = (tid < 64) ? mpos_b1[tid] : 0.0f;
        for (int idx = tid; idx < 64 * 128; idx += 256) {
            int k = idx >> 7, c = idx & 127;
            sh_W[idx] = (c < 64) ? mpos_w1[k * 64 + c]
                                 : mpos_w1[(64 + k) * 64 + (c - 64)];
        }
        for (int idx = tid; idx < 16 * 64; idx += 256) {
            int n = idx & 63, k4 = idx >> 6;
            int gn = nb + n;
            float4 v = make_float4(0.f, 0.f, 0.f, 0.f);
            if (gn < N) v = *(const float4*)(pe + (size_t)gn * 64 + 4 * k4);
            sh_inT[(4 * k4 + 0) * 68 + n] = v.x;
            sh_inT[(4 * k4 + 1) * 68 + n] = v.y;
            sh_inT[(4 * k4 + 2) * 68 + n] = v.z;
            sh_inT[(4 * k4 + 3) * 68 + n] = v.w;
        }
        __syncthreads();
        gemm_p8x4<64, 68, 128, 32>(sh_inT + r0, sh_W + c0, acc);
        dstA = g_P; dstB = g_Q;
    }

    float* dst = (c0 < 64) ? dstA : dstB;
    int lc = c0 & 63;
    float b0 = sh_b[c0], b1 = sh_b[c0 + 1], b2 = sh_b[c0 + 2], b3 = sh_b[c0 + 3];
    #pragma unroll
    for (int p = 0; p < 4; p++) {
        int rl = (p < 2) ? (r0 + 2 * p) : (32 + r0 + 2 * (p - 2));
        float lo0, hi0, lo1, hi1, lo2, hi2, lo3, hi3;
        unpack2(acc[p][0], lo0, hi0); unpack2(acc[p][1], lo1, hi1);
        unpack2(acc[p][2], lo2, hi2); unpack2(acc[p][3], lo3, hi3);
        int g0 = nb + rl, g1 = nb + rl + 1;
        if (g0 < N)
            *(float4*)(dst + (size_t)g0 * 64 + lc) =
                make_float4(lo0 + b0, lo1 + b1, lo2 + b2, lo3 + b3);
        if (g1 < N)
            *(float4*)(dst + (size_t)g1 * 64 + lc) =
                make_float4(hi0 + b0, hi1 + b1, hi2 + b2, hi3 + b3);
    }
}

// ============================================================
// Kernel 2: edge kernel — 4 CTAs/SM; ONE shared W buffer + ONE tile
// ============================================================
template <bool IS_TANH>
__device__ __forceinline__ void edge_gemm_path(
    const float* hT, const float* W, const float* bias, const int* recs,
    float* __restrict__ aggr, int r0, int c0, int eb, int E)
{
    ull_t acc[4][4];
    zero_acc(acc);
    gemm_p8x4_np<64, 132, 64, 64>(hT + r0, W + c0, acc);

    float b0 = bias[c0], b1 = bias[c0 + 1], b2 = bias[c0 + 2], b3 = bias[c0 + 3];
    #pragma unroll
    for (int p = 0; p < 4; p++) {
        int rl = (p < 2) ? (r0 + 2 * p) : (64 + r0 + 2 * (p - 2));
        float lo0, hi0, lo1, hi1, lo2, hi2, lo3, hi3;
        unpack2(acc[p][0], lo0, hi0); unpack2(acc[p][1], lo1, hi1);
        unpack2(acc[p][2], lo2, hi2); unpack2(acc[p][3], lo3, hi3);
        if (eb + rl < E) {
            float m0 = lo0 + b0, m1 = lo1 + b1, m2 = lo2 + b2, m3 = lo3 + b3;
            if (IS_TANH) { m0 = tanh_f(m0); m1 = tanh_f(m1); m2 = tanh_f(m2); m3 = tanh_f(m3); }
            else         { m0 = silu_f(m0); m1 = silu_f(m1); m2 = silu_f(m2); m3 = silu_f(m3); }
            float* dst = aggr + (size_t)recs[rl] * 64 + c0;
            asm volatile("red.global.add.v4.f32 [%0], {%1,%2,%3,%4};"
                         :: "l"(dst), "f"(m0), "f"(m1), "f"(m2), "f"(m3) : "memory");
        }
        if (eb + rl + 1 < E) {
            float m0 = hi0 + b0, m1 = hi1 + b1, m2 = hi2 + b2, m3 = hi3 + b3;
            if (IS_TANH) { m0 = tanh_f(m0); m1 = tanh_f(m1); m2 = tanh_f(m2); m3 = tanh_f(m3); }
            else         { m0 = silu_f(m0); m1 = silu_f(m1); m2 = silu_f(m2); m3 = silu_f(m3); }
            float* dst = aggr + (size_t)recs[rl + 1] * 64 + c0;
            asm volatile("red.global.add.v4.f32 [%0], {%1,%2,%3,%4};"
                         :: "l"(dst), "f"(m0), "f"(m1), "f"(m2), "f"(m3) : "memory");
        }
    }
}

__global__ void __launch_bounds__(256, 4) edge_kernel(
    const float* __restrict__ pos,
    const int* __restrict__ ei,          // int32 (JAX demotes int64)
    const float* __restrict__ msg_w1,
    const float* __restrict__ msg_w2, const float* __restrict__ msg_b2,
    const float* __restrict__ mpos_w1,
    const float* __restrict__ mpos_w2, const float* __restrict__ mpos_b2,
    int E)
{
    extern __shared__ float sm[];
    float* sh_t   = sm;                    // [64][132] (both paths)
    float* sh_W   = sh_t + 64 * 132;       // [64][64]  (Wm, then Wp)
    float* sh_we  = sh_W + 64 * 64;        // [64]
    float* sh_ve  = sh_we + 64;
    float* sh_bm  = sh_ve + 64;
    float* sh_bp  = sh_bm + 64;
    int*   sh_rec = (int*)(sh_bp + 64);    // [128]

    int tid = threadIdx.x;
    for (int i = tid; i < 64 * 64; i += 256) sh_W[i] = msg_w2[i];
    if (tid < 64) {
        sh_we[tid] = msg_w1[256 * 64 + tid];
        sh_ve[tid] = mpos_w1[128 * 64 + tid];
        sh_bm[tid] = msg_b2[tid];
        sh_bp[tid] = mpos_b2[tid];
    }

    int eb = blockIdx.x * 128;
    int e  = tid & 127;
    int half = tid >> 7;
    int eg = eb + e;
    bool valid = eg < E;
    int snd = 0, rcv = 0;
    if (valid) { snd = ei[eg]; rcv = ei[E + eg]; }
    if (half == 0) sh_rec[e] = rcv;
    float dist = 0.0f;
    if (valid) {
        float dx = pos[snd * 3 + 0] - pos[rcv * 3 + 0];
        float dy = pos[snd * 3 + 1] - pos[rcv * 3 + 1];
        float dz = pos[snd * 3 + 2] - pos[rcv * 3 + 2];
        dist = sqrtf(dx * dx + dy * dy + dz * dz);
    }
    __syncthreads();

    int c0h = half * 32;
    int tr = tid & 15, tc = tid >> 4;
    int r0 = 4 * tr, c0 = 4 * tc;

    // ---- phase A: silu(A[snd]+B[rcv]+dist*we), msg path ----
    {
        const float4* A4 = (const float4*)(g_A + (size_t)snd * 64 + c0h);
        const float4* B4 = (const float4*)(g_B + (size_t)rcv * 64 + c0h);
        const float4* W4 = (const float4*)(sh_we + c0h);
        #pragma unroll
        for (int j = 0; j < 8; j++) {
            float4 a = A4[j], b = B4[j], w = W4[j];
            float* dst = sh_t + (c0h + 4 * j) * 132 + e;
            dst[0]   = silu_f(a.x + b.x + dist * w.x);
            dst[132] = silu_f(a.y + b.y + dist * w.y);
            dst[264] = silu_f(a.z + b.z + dist * w.z);
            dst[396] = silu_f(a.w + b.w + dist * w.w);
        }
    }
    __syncthreads();
    edge_gemm_path<false>(sh_t, sh_W, sh_bm, sh_rec, g_aggr, r0, c0, eb, E);
    __syncthreads();

    // ---- phase B: load Wp over Wm; tanh(P[snd]+Q[rcv]+dist*ve) tile ----
    for (int i = tid; i < 64 * 64; i += 256) sh_W[i] = mpos_w2[i];
    {
        const float4* P4 = (const float4*)(g_P + (size_t)snd * 64 + c0h);
        const float4* Q4 = (const float4*)(g_Q + (size_t)rcv * 64 + c0h);
        const float4* V4 = (const float4*)(sh_ve + c0h);
        #pragma unroll
        for (int j = 0; j < 8; j++) {
            float4 p = P4[j], q = Q4[j], v = V4[j];
            float* dst = sh_t + (c0h + 4 * j) * 132 + e;
            dst[0]   = tanh_f(p.x + q.x + dist * v.x);
            dst[132] = tanh_f(p.y + q.y + dist * v.y);
            dst[264] = tanh_f(p.z + q.z + dist * v.z);
            dst[396] = tanh_f(p.w + q.w + dist * v.w);
        }
    }
    __syncthreads();
    edge_gemm_path<true>(sh_t, sh_W, sh_bp, sh_rec, g_aggrp, r0, c0, eb, E);
}

// ============================================================
// Kernel 3 (fused): blockIdx.y==0 -> update; ==1 -> update_pe
//   128 nodes/CTA.
// ============================================================
__global__ void __launch_bounds__(256, 3) upd_kernel(
    const float* __restrict__ x, const float* __restrict__ pe,
    const float* __restrict__ upd_w1, const float* __restrict__ upd_b1,
    const float* __restrict__ upd_w2, const float* __restrict__ upd_b2,
    const float* __restrict__ upe_w1, const float* __restrict__ upe_b1,
    const float* __restrict__ upe_w2, const float* __restrict__ upe_b2,
    float* __restrict__ out, int N)
{
    extern __shared__ float sm[];
    float* sh_inT = sm;                    // [64][132] (chunk; reused as hT)
    float* sh_Wc  = sh_inT + 64 * 132;     // [64][64]
    float* sh_b1  = sh_Wc + 64 * 64;       // [64]
    float* sh_b2  = sh_b1 + 64;            // [64]

    bool is_pe = (blockIdx.y != 0);
    const float* w1 = is_pe ? upe_w1 : upd_w1;
    const float* w2 = is_pe ? upe_w2 : upd_w2;
    int nchunks = is_pe ? 2 : 3;

    int tid = threadIdx.x;
    int nb = blockIdx.x * 128;
    if (tid < 64) {
        sh_b1[tid] = is_pe ? upe_b1[tid] : upd_b1[tid];
        sh_b2[tid] = is_pe ? upe_b2[tid] : upd_b2[tid];
    }

    int tr = tid & 15, tc = tid >> 4;
    int r0 = 4 * tr, c0 = 4 * tc;

    ull_t acc[4][4];
    zero_acc(acc);

    #pragma unroll 1
    for (int ch = 0; ch < nchunks; ch++) {
        __syncthreads();
        for (int idx = tid; idx < 64 * 64; idx += 256)
            sh_Wc[idx] = w1[ch * 64 * 64 + idx];
        const float* src = is_pe ? ((ch == 0) ? pe : g_aggrp)
                                 : ((ch == 0) ? x : (ch == 1) ? pe : g_aggr);
        for (int idx = tid; idx < 16 * 128; idx += 256) {
            int n = idx & 127, k4 = idx >> 7;
            int gn = nb + n;
            float4 v = make_float4(0.f, 0.f, 0.f, 0.f);
            if (gn < N) v = *(const float4*)(src + (size_t)gn * 64 + 4 * k4);
            sh_inT[(4 * k4 + 0) * 132 + n] = v.x;
            sh_inT[(4 * k4 + 1) * 132 + n] = v.y;
            sh_inT[(4 * k4 + 2) * 132 + n] = v.z;
            sh_inT[(4 * k4 + 3) * 132 + n] = v.w;
        }
        __syncthreads();
        gemm_p8x4<64, 132, 64, 64>(sh_inT + r0, sh_Wc + c0, acc);
    }

    __syncthreads();   // all reads of inT done before overwrite as hT
    // activation + write hT: per col c, rows r0..r0+3 from acc[0..1][c] (lo,hi),
    // rows 64+r0..64+r0+3 from acc[2..3][c].
    #pragma unroll
    for (int c = 0; c < 4; c++) {
        float bj = sh_b1[c0 + c];
        float v0, v1, v2, v3, v4, v5, v6, v7;
        unpack2(acc[0][c], v0, v1); unpack2(acc[1][c], v2, v3);
        unpack2(acc[2][c], v4, v5); unpack2(acc[3][c], v6, v7);
        if (is_pe) {
            v0 = tanh_f(v0 + bj); v1 = tanh_f(v1 + bj); v2 = tanh_f(v2 + bj); v3 = tanh_f(v3 + bj);
            v4 = tanh_f(v4 + bj); v5 = tanh_f(v5 + bj); v6 = tanh_f(v6 + bj); v7 = tanh_f(v7 + bj);
        } else {
            v0 = silu_f(v0 + bj); v1 = silu_f(v1 + bj); v2 = silu_f(v2 + bj); v3 = silu_f(v3 + bj);
            v4 = silu_f(v4 + bj); v5 = silu_f(v5 + bj); v6 = silu_f(v6 + bj); v7 = silu_f(v7 + bj);
        }
        float* d = sh_inT + (c0 + c) * 132;
        *(float4*)(d + r0)      = make_float4(v0, v1, v2, v3);
        *(float4*)(d + 64 + r0) = make_float4(v4, v5, v6, v7);
    }
    for (int idx = tid; idx < 64 * 64; idx += 256) sh_Wc[idx] = w2[idx];
    __syncthreads();

    ull_t a2[4][4];
    zero_acc(a2);
    gemm_p8x4<64, 132, 64, 64>(sh_inT + r0, sh_Wc + c0, a2);

    float b0 = sh_b2[c0], b1 = sh_b2[c0 + 1], b2 = sh_b2[c0 + 2], b3 = sh_b2[c0 + 3];
    float* obase = out + (is_pe ? (size_t)N * 64 : 0);
    #pragma unroll
    for (int p = 0; p < 4; p++) {
        int rl = (p < 2) ? (r0 + 2 * p) : (64 + r0 + 2 * (p - 2));
        float lo0, hi0, lo1, hi1, lo2, hi2, lo3, hi3;
        unpack2(a2[p][0], lo0, hi0); unpack2(a2[p][1], lo1, hi1);
        unpack2(a2[p][2], lo2, hi2); unpack2(a2[p][3], lo3, hi3);
        int g0 = nb + rl, g1 = nb + rl + 1;
        if (g0 < N) {
            float o0 = lo0 + b0, o1 = lo1 + b1, o2 = lo2 + b2, o3 = lo3 + b3;
            if (is_pe) { o0 = tanh_f(o0); o1 = tanh_f(o1); o2 = tanh_f(o2); o3 = tanh_f(o3); }
            *(float4*)(obase + (size_t)g0 * 64 + c0) = make_float4(o0, o1, o2, o3);
        }
        if (g1 < N) {
            float o0 = hi0 + b0, o1 = hi1 + b1, o2 = hi2 + b2, o3 = hi3 + b3;
            if (is_pe) { o0 = tanh_f(o0); o1 = tanh_f(o1); o2 = tanh_f(o2); o3 = tanh_f(o3); }
            *(float4*)(obase + (size_t)g1 * 64 + c0) = make_float4(o0, o1, o2, o3);
        }
    }
}

// ============================================================
// Host launch
// ============================================================
extern "C" void kernel_launch(void* const* d_in, const int* in_sizes, int n_in,
                              void* d_out, int out_size)
{
    const float* x       = (const float*)d_in[0];
    const float* pos     = (const float*)d_in[1];
    const float* pe      = (const float*)d_in[2];
    const int*   ei      = (const int*)d_in[3];
    const float* msg_w1  = (const float*)d_in[4];
    const float* msg_b1  = (const float*)d_in[5];
    const float* msg_w2  = (const float*)d_in[6];
    const float* msg_b2  = (const float*)d_in[7];
    const float* mpos_w1 = (const float*)d_in[8];
    const float* mpos_b1 = (const float*)d_in[9];
    const float* mpos_w2 = (const float*)d_in[10];
    const float* mpos_b2 = (const float*)d_in[11];
    const float* upd_w1  = (const float*)d_in[12];
    const float* upd_b1  = (const float*)d_in[13];
    const float* upd_w2  = (const float*)d_in[14];
    const float* upd_b2  = (const float*)d_in[15];
    const float* upe_w1  = (const float*)d_in[16];
    const float* upe_b1  = (const float*)d_in[17];
    const float* upe_w2  = (const float*)d_in[18];
    const float* upe_b2  = (const float*)d_in[19];

    int N = in_sizes[0] / 64;
    int E = in_sizes[3] / 2;

    const int SMEM_PRE  = (64 * 68 + 64 * 128 + 128) * 4;            // 50,688 B
    const int SMEM_EDGE = (64 * 132 + 64 * 64 + 256) * 4 + 512;      // 51,712 B
    const int SMEM_UPD  = (64 * 132 + 64 * 64 + 128) * 4;            // 50,688 B

    cudaFuncSetAttribute(pre_kernel,  cudaFuncAttributeMaxDynamicSharedMemorySize, SMEM_PRE);
    cudaFuncSetAttribute(edge_kernel, cudaFuncAttributeMaxDynamicSharedMemorySize, SMEM_EDGE);
    cudaFuncSetAttribute(upd_kernel,  cudaFuncAttributeMaxDynamicSharedMemorySize, SMEM_UPD);

    dim3 gpre((N + 63) / 64, 2);
    dim3 gupd((N + 127) / 128, 2);
    pre_kernel<<<gpre, 256, SMEM_PRE>>>(x, pe, msg_w1, msg_b1, mpos_w1, mpos_b1, N);
    edge_kernel<<<(E + 127) / 128, 256, SMEM_EDGE>>>(pos, ei, msg_w1, msg_w2, msg_b2,
                                                     mpos_w1, mpos_w2, mpos_b2, E);
    upd_kernel<<<gupd, 256, SMEM_UPD>>>(x, pe, upd_w1, upd_b1, upd_w2, upd_b2,
                                        upe_w1, upe_b1, upe_w2, upe_b2,
                                        (float*)d_out, N);
}

// round 11
// speedup vs baseline: 1.1363x; 1.1363x over previous
#include <cuda_runtime.h>
#include <cstdint>

#define NV_MAX 50000
#define HDIM 64

// -------- scratch (no allocs allowed) --------
__device__ float g_A[NV_MAX * HDIM];
__device__ float g_B[NV_MAX * HDIM];
__device__ float g_P[NV_MAX * HDIM];
__device__ float g_Q[NV_MAX * HDIM];
__device__ float g_aggr[NV_MAX * HDIM];
__device__ float g_aggrp[NV_MAX * HDIM];

typedef unsigned long long ull_t;

__device__ __forceinline__ ull_t pack2(float lo, float hi) {
    ull_t r; asm("mov.b64 %0, {%1, %2};" : "=l"(r) : "f"(lo), "f"(hi)); return r;
}
__device__ __forceinline__ void unpack2(ull_t v, float& lo, float& hi) {
    asm("mov.b64 {%0, %1}, %2;" : "=f"(lo), "=f"(hi) : "l"(v));
}
__device__ __forceinline__ ull_t ffma2(ull_t a, ull_t b, ull_t c) {
    ull_t d; asm("fma.rn.f32x2 %0, %1, %2, %3;" : "=l"(d) : "l"(a), "l"(b), "l"(c)); return d;
}
__device__ __forceinline__ float tanh_f(float x) {
    float y; asm("tanh.approx.f32 %0, %1;" : "=f"(y) : "f"(x)); return y;
}
__device__ __forceinline__ float silu_f(float x) {
    return 0.5f * x * (1.0f + tanh_f(0.5f * x));   // single MUFU
}
__device__ __forceinline__ uint32_t f2tf32(float x) {
    uint32_t r; asm("cvt.rna.tf32.f32 %0, %1;" : "=r"(r) : "f"(x)); return r;
}
__device__ __forceinline__ void mma_tf32(float c[4],
    uint32_t a0, uint32_t a1, uint32_t a2, uint32_t a3, uint32_t b0, uint32_t b1)
{
    asm volatile(
        "mma.sync.aligned.m16n8k8.row.col.f32.tf32.tf32.f32 "
        "{%0,%1,%2,%3}, {%4,%5,%6,%7}, {%8,%9}, {%0,%1,%2,%3};"
        : "+f"(c[0]), "+f"(c[1]), "+f"(c[2]), "+f"(c[3])
        : "r"(a0), "r"(a1), "r"(a2), "r"(a3), "r"(b0), "r"(b1));
}

// ---------------- R9 champion FFMA2 microkernel (pre/upd) ----------------
#define FFMA2_BLOCK(ha, hb, w)                                              \
    {                                                                       \
        ull_t p0 = pack2(ha.x, ha.x), p1 = pack2(ha.y, ha.y);               \
        ull_t p2 = pack2(ha.z, ha.z), p3 = pack2(ha.w, ha.w);               \
        ull_t p4 = pack2(hb.x, hb.x), p5 = pack2(hb.y, hb.y);               \
        ull_t p6 = pack2(hb.z, hb.z), p7 = pack2(hb.w, hb.w);               \
        acc[0][0] = ffma2(p0, w.x, acc[0][0]); acc[0][1] = ffma2(p0, w.y, acc[0][1]); \
        acc[1][0] = ffma2(p1, w.x, acc[1][0]); acc[1][1] = ffma2(p1, w.y, acc[1][1]); \
        acc[2][0] = ffma2(p2, w.x, acc[2][0]); acc[2][1] = ffma2(p2, w.y, acc[2][1]); \
        acc[3][0] = ffma2(p3, w.x, acc[3][0]); acc[3][1] = ffma2(p3, w.y, acc[3][1]); \
        acc[4][0] = ffma2(p4, w.x, acc[4][0]); acc[4][1] = ffma2(p4, w.y, acc[4][1]); \
        acc[5][0] = ffma2(p5, w.x, acc[5][0]); acc[5][1] = ffma2(p5, w.y, acc[5][1]); \
        acc[6][0] = ffma2(p6, w.x, acc[6][0]); acc[6][1] = ffma2(p6, w.y, acc[6][1]); \
        acc[7][0] = ffma2(p7, w.x, acc[7][0]); acc[7][1] = ffma2(p7, w.y, acc[7][1]); \
    }

template <int K, int ISTRIDE, int WSTRIDE, int HALF>
__device__ __forceinline__ void gemm_8x4(
    const float* __restrict__ inT, const float* __restrict__ W, ull_t acc[8][2])
{
    float4 ha = *(const float4*)(inT);
    float4 hb = *(const float4*)(inT + HALF);
    ulonglong2 w = *(const ulonglong2*)(W);
    #pragma unroll 8
    for (int k = 0; k < K; k++) {
        float4 nha, nhb; ulonglong2 nw;
        if (k + 1 < K) {
            nha = *(const float4*)(inT + (k + 1) * ISTRIDE);
            nhb = *(const float4*)(inT + (k + 1) * ISTRIDE + HALF);
            nw  = *(const ulonglong2*)(W + (k + 1) * WSTRIDE);
        }
        FFMA2_BLOCK(ha, hb, w);
        ha = nha; hb = nhb; w = nw;
    }
}

__device__ __forceinline__ void zero_acc(ull_t acc[8][2]) {
    #pragma unroll
    for (int i = 0; i < 8; i++) { acc[i][0] = 0ULL; acc[i][1] = 0ULL; }
}

// ============================================================
// Kernel 1 (fused): blockIdx.y==0 -> A,B (+zero aggr); ==1 -> P,Q
// ============================================================
__global__ void __launch_bounds__(256, 3) pre_kernel(
    const float* __restrict__ x, const float* __restrict__ pe,
    const float* __restrict__ msg_w1, const float* __restrict__ msg_b1,
    const float* __restrict__ mpos_w1, const float* __restrict__ mpos_b1,
    int N)
{
    extern __shared__ float sm[];
    float* sh_inT = sm;                   // [64][68]
    float* sh_W   = sh_inT + 64 * 68;     // [64][128]
    float* sh_b   = sh_W + 64 * 128;      // [128]

    int tid = threadIdx.x;
    int nb = blockIdx.x * 64;
    int tr = tid & 7, tc = tid >> 3;
    int r0 = 4 * tr, c0 = 4 * tc;

    ull_t acc[8][2];
    zero_acc(acc);
    float* dstA;
    float* dstB;

    if (blockIdx.y == 0) {
        if (tid < 128) sh_b[tid] = (tid < 64) ? msg_b1[tid] : 0.0f;
        for (int idx = tid; idx < 2048; idx += 256) {
            int n = idx & 63, s = (idx >> 6) & 15, which = idx >> 10;
            int gn = nb + n;
            if (gn < N) {
                float4* dst = (float4*)((which ? g_aggrp : g_aggr) + (size_t)gn * 64) + s;
                *dst = make_float4(0.f, 0.f, 0.f, 0.f);
            }
        }
        #pragma unroll 1
        for (int ch = 0; ch < 2; ch++) {
            __syncthreads();
            for (int idx = tid; idx < 64 * 128; idx += 256) {
                int k = idx >> 7, c = idx & 127;
                sh_W[idx] = (c < 64) ? msg_w1[(ch * 64 + k) * 64 + c]
                                     : msg_w1[(128 + ch * 64 + k) * 64 + (c - 64)];
            }
            const float* src = (ch == 0) ? x : pe;
            for (int idx = tid; idx < 16 * 64; idx += 256) {
                int n = idx & 63, k4 = idx >> 6;
                int gn = nb + n;
                float4 v = make_float4(0.f, 0.f, 0.f, 0.f);
                if (gn < N) v = *(const float4*)(src + (size_t)gn * 64 + 4 * k4);
                sh_inT[(4 * k4 + 0) * 68 + n] = v.x;
                sh_inT[(4 * k4 + 1) * 68 + n] = v.y;
                sh_inT[(4 * k4 + 2) * 68 + n] = v.z;
                sh_inT[(4 * k4 + 3) * 68 + n] = v.w;
            }
            __syncthreads();
            gemm_8x4<64, 68, 128, 32>(sh_inT + r0, sh_W + c0, acc);
        }
        dstA = g_A; dstB = g_B;
    } else {
        if (tid < 128) sh_b[tid] = (tid < 64) ? mpos_b1[tid] : 0.0f;
        for (int idx = tid; idx < 64 * 128; idx += 256) {
            int k = idx >> 7, c = idx & 127;
            sh_W[idx] = (c < 64) ? mpos_w1[k * 64 + c]
                                 : mpos_w1[(64 + k) * 64 + (c - 64)];
        }
        for (int idx = tid; idx < 16 * 64; idx += 256) {
            int n = idx & 63, k4 = idx >> 6;
            int gn = nb + n;
            float4 v = make_float4(0.f, 0.f, 0.f, 0.f);
            if (gn < N) v = *(const float4*)(pe + (size_t)gn * 64 + 4 * k4);
            sh_inT[(4 * k4 + 0) * 68 + n] = v.x;
            sh_inT[(4 * k4 + 1) * 68 + n] = v.y;
            sh_inT[(4 * k4 + 2) * 68 + n] = v.z;
            sh_inT[(4 * k4 + 3) * 68 + n] = v.w;
        }
        __syncthreads();
        gemm_8x4<64, 68, 128, 32>(sh_inT + r0, sh_W + c0, acc);
        dstA = g_P; dstB = g_Q;
    }

    float* dst = (c0 < 64) ? dstA : dstB;
    int lc = c0 & 63;
    float b0 = sh_b[c0], b1 = sh_b[c0 + 1], b2 = sh_b[c0 + 2], b3 = sh_b[c0 + 3];
    #pragma unroll
    for (int i = 0; i < 8; i++) {
        int rr = (i < 4) ? (r0 + i) : (32 + r0 + i - 4);
        int gn = nb + rr;
        if (gn < N) {
            float o0, o1, o2, o3;
            unpack2(acc[i][0], o0, o1);
            unpack2(acc[i][1], o2, o3);
            *(float4*)(dst + (size_t)gn * 64 + lc) =
                make_float4(o0 + b0, o1 + b1, o2 + b2, o3 + b3);
        }
    }
}

// ============================================================
// Kernel 2: edge kernel — tf32 mma (3xTF32 split) layer-2 GEMMs
// ============================================================
// W fragments pre-arranged per-lane in smem: for each (kt, nt), lane l holds
// float2( W[8kt+tig][8nt+gid], W[8kt+tig+4][8nt+gid] ), gid=l>>2, tig=l&3.
// -> consecutive lanes read consecutive float2: conflict-free LDS.64.
__device__ __forceinline__ void build_wfrag(
    const float* __restrict__ Wsrc, float* __restrict__ sh_Whi,
    float* __restrict__ sh_Wlo, int tid)
{
    for (int idx = tid; idx < 2048; idx += 256) {
        int kt = idx >> 8;
        int nt = (idx >> 5) & 7;
        int ln = idx & 31;
        int g = ln >> 2, t = ln & 3;
        int r = 8 * kt + t, c = 8 * nt + g;
        float w0 = Wsrc[r * 64 + c];
        float w1 = Wsrc[(r + 4) * 64 + c];
        uint32_t h0 = f2tf32(w0), h1 = f2tf32(w1);
        uint32_t l0 = f2tf32(w0 - __uint_as_float(h0));
        uint32_t l1 = f2tf32(w1 - __uint_as_float(h1));
        sh_Whi[2 * idx]     = __uint_as_float(h0);
        sh_Whi[2 * idx + 1] = __uint_as_float(h1);
        sh_Wlo[2 * idx]     = __uint_as_float(l0);
        sh_Wlo[2 * idx + 1] = __uint_as_float(l1);
    }
}

template <bool IS_TANH>
__device__ __forceinline__ void edge_mma_path(
    const float* __restrict__ sh_t, const float* __restrict__ sh_Whi,
    const float* __restrict__ sh_Wlo, const float* __restrict__ bias,
    const int* __restrict__ rec, float* __restrict__ aggr,
    int w, int lane, int eb, int E)
{
    int gid = lane >> 2, tig = lane & 3;
    int e0 = w * 16;

    float acc[8][4];
    #pragma unroll
    for (int nt = 0; nt < 8; nt++) {
        acc[nt][0] = 0.f; acc[nt][1] = 0.f; acc[nt][2] = 0.f; acc[nt][3] = 0.f;
    }

    #pragma unroll 2
    for (int kt = 0; kt < 8; kt++) {
        const float* tk = sh_t + (8 * kt + tig) * 132 + e0 + gid;
        float a0f = tk[0],       a1f = tk[8];
        float a2f = tk[4 * 132], a3f = tk[4 * 132 + 8];
        uint32_t a0h = f2tf32(a0f), a1h = f2tf32(a1f);
        uint32_t a2h = f2tf32(a2f), a3h = f2tf32(a3f);
        uint32_t a0l = f2tf32(a0f - __uint_as_float(a0h));
        uint32_t a1l = f2tf32(a1f - __uint_as_float(a1h));
        uint32_t a2l = f2tf32(a2f - __uint_as_float(a2h));
        uint32_t a3l = f2tf32(a3f - __uint_as_float(a3h));
        #pragma unroll
        for (int nt = 0; nt < 8; nt++) {
            int fo = ((kt * 8 + nt) * 32 + lane) * 2;
            float2 bh = *(const float2*)(sh_Whi + fo);
            float2 bl = *(const float2*)(sh_Wlo + fo);
            uint32_t bh0 = __float_as_uint(bh.x), bh1 = __float_as_uint(bh.y);
            uint32_t bl0 = __float_as_uint(bl.x), bl1 = __float_as_uint(bl.y);
            mma_tf32(acc[nt], a0h, a1h, a2h, a3h, bh0, bh1);
            mma_tf32(acc[nt], a0h, a1h, a2h, a3h, bl0, bl1);
            mma_tf32(acc[nt], a0l, a1l, a2l, a3l, bh0, bh1);
        }
    }

    int el0 = e0 + gid, el1 = el0 + 8;
    bool v0 = (eb + el0 < E), v1 = (eb + el1 < E);
    int rc0 = rec[el0], rc1 = rec[el1];
    #pragma unroll
    for (int nt = 0; nt < 8; nt++) {
        int c = 8 * nt + 2 * tig;
        float b0 = bias[c], b1 = bias[c + 1];
        if (v0) {
            float m0 = acc[nt][0] + b0, m1 = acc[nt][1] + b1;
            if (IS_TANH) { m0 = tanh_f(m0); m1 = tanh_f(m1); }
            else         { m0 = silu_f(m0); m1 = silu_f(m1); }
            float* dst = aggr + (size_t)rc0 * 64 + c;
            asm volatile("red.global.add.v2.f32 [%0], {%1,%2};"
                         :: "l"(dst), "f"(m0), "f"(m1) : "memory");
        }
        if (v1) {
            float m0 = acc[nt][2] + b0, m1 = acc[nt][3] + b1;
            if (IS_TANH) { m0 = tanh_f(m0); m1 = tanh_f(m1); }
            else         { m0 = silu_f(m0); m1 = silu_f(m1); }
            float* dst = aggr + (size_t)rc1 * 64 + c;
            asm volatile("red.global.add.v2.f32 [%0], {%1,%2};"
                         :: "l"(dst), "f"(m0), "f"(m1) : "memory");
        }
    }
}

__global__ void __launch_bounds__(256, 3) edge_kernel(
    const float* __restrict__ pos,
    const int* __restrict__ ei,          // int32 (JAX demotes int64)
    const float* __restrict__ msg_w1,
    const float* __restrict__ msg_w2, const float* __restrict__ msg_b2,
    const float* __restrict__ mpos_w1,
    const float* __restrict__ mpos_w2, const float* __restrict__ mpos_b2,
    int E)
{
    extern __shared__ float sm[];
    float* sh_t   = sm;                    // [64][132]
    float* sh_Whi = sh_t + 64 * 132;       // 4096 (per-lane W frags, hi)
    float* sh_Wlo = sh_Whi + 4096;         // 4096 (lo)
    float* sh_we  = sh_Wlo + 4096;         // [64]
    float* sh_ve  = sh_we + 64;
    float* sh_bm  = sh_ve + 64;
    float* sh_bp  = sh_bm + 64;
    int*   sh_rec = (int*)(sh_bp + 64);    // [128]

    int tid = threadIdx.x;
    build_wfrag(msg_w2, sh_Whi, sh_Wlo, tid);
    if (tid < 64) {
        sh_we[tid] = msg_w1[256 * 64 + tid];   // dist row of msg_w1
        sh_ve[tid] = mpos_w1[128 * 64 + tid];  // dist row of mpos_w1
        sh_bm[tid] = msg_b2[tid];
        sh_bp[tid] = mpos_b2[tid];
    }

    int eb = blockIdx.x * 128;
    int e  = tid & 127;
    int half = tid >> 7;
    int eg = eb + e;
    bool valid = eg < E;
    int snd = 0, rcv = 0;
    if (valid) { snd = ei[eg]; rcv = ei[E + eg]; }
    if (half == 0) sh_rec[e] = rcv;
    float dist = 0.0f;
    if (valid) {
        float dx = pos[snd * 3 + 0] - pos[rcv * 3 + 0];
        float dy = pos[snd * 3 + 1] - pos[rcv * 3 + 1];
        float dz = pos[snd * 3 + 2] - pos[rcv * 3 + 2];
        dist = sqrtf(dx * dx + dy * dy + dz * dz);
    }
    __syncthreads();

    int c0h = half * 32;
    int w = tid >> 5, lane = tid & 31;

    // ---- phase A: silu(A[snd]+B[rcv]+dist*we) -> sh_t, then msg GEMM ----
    {
        const float4* A4 = (const float4*)(g_A + (size_t)snd * 64 + c0h);
        const float4* B4 = (const float4*)(g_B + (size_t)rcv * 64 + c0h);
        const float4* W4 = (const float4*)(sh_we + c0h);
        #pragma unroll
        for (int j = 0; j < 8; j++) {
            float4 a = A4[j], b = B4[j], wv = W4[j];
            float* dst = sh_t + (c0h + 4 * j) * 132 + e;
            dst[0]   = silu_f(a.x + b.x + dist * wv.x);
            dst[132] = silu_f(a.y + b.y + dist * wv.y);
            dst[264] = silu_f(a.z + b.z + dist * wv.z);
            dst[396] = silu_f(a.w + b.w + dist * wv.w);
        }
    }
    __syncthreads();
    edge_mma_path<false>(sh_t, sh_Whi, sh_Wlo, sh_bm, sh_rec, g_aggr, w, lane, eb, E);
    __syncthreads();   // all reads of sh_t / W frags complete

    // ---- phase B: rebuild W frags from mpos_w2; tanh tile; pos GEMM ----
    build_wfrag(mpos_w2, sh_Whi, sh_Wlo, tid);
    {
        const float4* P4 = (const float4*)(g_P + (size_t)snd * 64 + c0h);
        const float4* Q4 = (const float4*)(g_Q + (size_t)rcv * 64 + c0h);
        const float4* V4 = (const float4*)(sh_ve + c0h);
        #pragma unroll
        for (int j = 0; j < 8; j++) {
            float4 p = P4[j], q = Q4[j], v = V4[j];
            float* dst = sh_t + (c0h + 4 * j) * 132 + e;
            dst[0]   = tanh_f(p.x + q.x + dist * v.x);
            dst[132] = tanh_f(p.y + q.y + dist * v.y);
            dst[264] = tanh_f(p.z + q.z + dist * v.z);
            dst[396] = tanh_f(p.w + q.w + dist * v.w);
        }
    }
    __syncthreads();
    edge_mma_path<true>(sh_t, sh_Whi, sh_Wlo, sh_bp, sh_rec, g_aggrp, w, lane, eb, E);
}

// ============================================================
// Kernel 3 (fused): blockIdx.y==0 -> update; ==1 -> update_pe
// ============================================================
__global__ void __launch_bounds__(256, 3) upd_kernel(
    const float* __restrict__ x, const float* __restrict__ pe,
    const float* __restrict__ upd_w1, const float* __restrict__ upd_b1,
    const float* __restrict__ upd_w2, const float* __restrict__ upd_b2,
    const float* __restrict__ upe_w1, const float* __restrict__ upe_b1,
    const float* __restrict__ upe_w2, const float* __restrict__ upe_b2,
    float* __restrict__ out, int N)
{
    extern __shared__ float sm[];
    float* sh_inT = sm;                    // [64][132]
    float* sh_Wc  = sh_inT + 64 * 132;     // [64][64]
    float* sh_b1  = sh_Wc + 64 * 64;       // [64]
    float* sh_b2  = sh_b1 + 64;            // [64]

    bool is_pe = (blockIdx.y != 0);
    const float* w1 = is_pe ? upe_w1 : upd_w1;
    const float* w2 = is_pe ? upe_w2 : upd_w2;
    int nchunks = is_pe ? 2 : 3;

    int tid = threadIdx.x;
    int nb = blockIdx.x * 128;
    if (tid < 64) {
        sh_b1[tid] = is_pe ? upe_b1[tid] : upd_b1[tid];
        sh_b2[tid] = is_pe ? upe_b2[tid] : upd_b2[tid];
    }

    int tr = tid & 15, tc = tid >> 4;
    int r0 = 4 * tr, c0 = 4 * tc;

    ull_t acc[8][2];
    zero_acc(acc);

    #pragma unroll 1
    for (int ch = 0; ch < nchunks; ch++) {
        __syncthreads();
        for (int idx = tid; idx < 64 * 64; idx += 256)
            sh_Wc[idx] = w1[ch * 64 * 64 + idx];
        const float* src = is_pe ? ((ch == 0) ? pe : g_aggrp)
                                 : ((ch == 0) ? x : (ch == 1) ? pe : g_aggr);
        for (int idx = tid; idx < 16 * 128; idx += 256) {
            int n = idx & 127, k4 = idx >> 7;
            int gn = nb + n;
            float4 v = make_float4(0.f, 0.f, 0.f, 0.f);
            if (gn < N) v = *(const float4*)(src + (size_t)gn * 64 + 4 * k4);
            sh_inT[(4 * k4 + 0) * 132 + n] = v.x;
            sh_inT[(4 * k4 + 1) * 132 + n] = v.y;
            sh_inT[(4 * k4 + 2) * 132 + n] = v.z;
            sh_inT[(4 * k4 + 3) * 132 + n] = v.w;
        }
        __syncthreads();
        gemm_8x4<64, 132, 64, 64>(sh_inT + r0, sh_Wc + c0, acc);
    }

    __syncthreads();
    #pragma unroll
    for (int j = 0; j < 2; j++) {
        float bj0 = sh_b1[c0 + 2 * j], bj1 = sh_b1[c0 + 2 * j + 1];
        float lo[8], hi[8];
        #pragma unroll
        for (int i = 0; i < 8; i++) { unpack2(acc[i][j], lo[i], hi[i]); }
        #pragma unroll
        for (int i = 0; i < 8; i++) {
            lo[i] = is_pe ? tanh_f(lo[i] + bj0) : silu_f(lo[i] + bj0);
            hi[i] = is_pe ? tanh_f(hi[i] + bj1) : silu_f(hi[i] + bj1);
        }
        float* d0 = sh_inT + (c0 + 2 * j) * 132;
        float* d1 = d0 + 132;
        *(float4*)(d0 + r0)      = make_float4(lo[0], lo[1], lo[2], lo[3]);
        *(float4*)(d0 + 64 + r0) = make_float4(lo[4], lo[5], lo[6], lo[7]);
        *(float4*)(d1 + r0)      = make_float4(hi[0], hi[1], hi[2], hi[3]);
        *(float4*)(d1 + 64 + r0) = make_float4(hi[4], hi[5], hi[6], hi[7]);
    }
    for (int idx = tid; idx < 64 * 64; idx += 256) sh_Wc[idx] = w2[idx];
    __syncthreads();

    ull_t a2[8][2];
    zero_acc(a2);
    gemm_8x4<64, 132, 64, 64>(sh_inT + r0, sh_Wc + c0, a2);

    float b0 = sh_b2[c0], b1 = sh_b2[c0 + 1], b2 = sh_b2[c0 + 2], b3 = sh_b2[c0 + 3];
    float* obase = out + (is_pe ? (size_t)N * 64 : 0);
    #pragma unroll
    for (int i = 0; i < 8; i++) {
        int rr = (i < 4) ? (r0 + i) : (64 + r0 + i - 4);
        int g = nb + rr;
        if (g < N) {
            float o0, o1, o2, o3;
            unpack2(a2[i][0], o0, o1);
            unpack2(a2[i][1], o2, o3);
            if (is_pe) { o0 = tanh_f(o0 + b0); o1 = tanh_f(o1 + b1);
                         o2 = tanh_f(o2 + b2); o3 = tanh_f(o3 + b3); }
            else       { o0 += b0; o1 += b1; o2 += b2; o3 += b3; }
            *(float4*)(obase + (size_t)g * 64 + c0) = make_float4(o0, o1, o2, o3);
        }
    }
}

// ============================================================
// Host launch
// ============================================================
extern "C" void kernel_launch(void* const* d_in, const int* in_sizes, int n_in,
                              void* d_out, int out_size)
{
    const float* x       = (const float*)d_in[0];
    const float* pos     = (const float*)d_in[1];
    const float* pe      = (const float*)d_in[2];
    const int*   ei      = (const int*)d_in[3];
    const float* msg_w1  = (const float*)d_in[4];
    const float* msg_b1  = (const float*)d_in[5];
    const float* msg_w2  = (const float*)d_in[6];
    const float* msg_b2  = (const float*)d_in[7];
    const float* mpos_w1 = (const float*)d_in[8];
    const float* mpos_b1 = (const float*)d_in[9];
    const float* mpos_w2 = (const float*)d_in[10];
    const float* mpos_b2 = (const float*)d_in[11];
    const float* upd_w1  = (const float*)d_in[12];
    const float* upd_b1  = (const float*)d_in[13];
    const float* upd_w2  = (const float*)d_in[14];
    const float* upd_b2  = (const float*)d_in[15];
    const float* upe_w1  = (const float*)d_in[16];
    const float* upe_b1  = (const float*)d_in[17];
    const float* upe_w2  = (const float*)d_in[18];
    const float* upe_b2  = (const float*)d_in[19];

    int N = in_sizes[0] / 64;
    int E = in_sizes[3] / 2;

    const int SMEM_PRE  = (64 * 68 + 64 * 128 + 128) * 4;                  // 50,688 B
    const int SMEM_EDGE = (64 * 132 + 4096 + 4096 + 256) * 4 + 512;        // 68,096 B
    const int SMEM_UPD  = (64 * 132 + 64 * 64 + 128) * 4;                  // 50,688 B

    cudaFuncSetAttribute(pre_kernel,  cudaFuncAttributeMaxDynamicSharedMemorySize, SMEM_PRE);
    cudaFuncSetAttribute(edge_kernel, cudaFuncAttributeMaxDynamicSharedMemorySize, SMEM_EDGE);
    cudaFuncSetAttribute(upd_kernel,  cudaFuncAttributeMaxDynamicSharedMemorySize, SMEM_UPD);

    dim3 gpre((N + 63) / 64, 2);
    dim3 gupd((N + 127) / 128, 2);
    pre_kernel<<<gpre, 256, SMEM_PRE>>>(x, pe, msg_w1, msg_b1, mpos_w1, mpos_b1, N);
    edge_kernel<<<(E + 127) / 128, 256, SMEM_EDGE>>>(pos, ei, msg_w1, msg_w2, msg_b2,
                                                     mpos_w1, mpos_w2, mpos_b2, E);
    upd_kernel<<<gupd, 256, SMEM_UPD>>>(x, pe, upd_w1, upd_b1, upd_w2, upd_b2,
                                        upe_w1, upe_b1, upe_w2, upe_b2,
                                        (float*)d_out, N);
}